// round 13
// baseline (speedup 1.0000x reference)
#include <cuda_runtime.h>

// PixelWiseNet: out[h,w] = bias + sum_{c,k} p_a[c,k]*relu(x[c,h,w]*rowsum(M[c]) + bias_c[c] - p_t[c,k])
// C=3, H=W=1024, K=16.  Output [1024,1024] f32.
//
// PWL-in-x per channel: g_c(x) = A[j]*x + B[j], j = #{r: xb_r <= x} (xb sorted).
// Sign of scale folded into table build; bias + scale==0 constants in channel-0 B.
// R11: compares emitted as FSET (set.ge.u32.f32 -> 0/-1) + IADD3 counting,
// cutting the per-value search from ~27 to ~17 issue slots. Two 4-pixel groups
// to keep regs ~40.

#define C 3
#define K 16
#define HW (1024 * 1024)
#define N4 (HW / 4)
#define THREADS 256
#define PXT 2
#define BLOCKS (N4 / (THREADS * PXT))   // 512

__device__ __forceinline__ int cmp_ge_mask(float u, float t) {
    int r;
    asm("set.ge.u32.f32 %0, %1, %2;" : "=r"(r) : "f"(u), "f"(t));
    return r;   // 0xFFFFFFFF (=-1) if u >= t else 0
}

// j = #{r in [0,16): st[r] <= u} via 3 register pivots + one LDS.128 quartile.
__device__ __forceinline__ float2 pwl_coeff(float u, float p0, float p1, float p2,
                                            const float4* __restrict__ st4c,
                                            const float2* __restrict__ ab) {
    int m = -(cmp_ge_mask(u, p0) + cmp_ge_mask(u, p1) + cmp_ge_mask(u, p2));
    float4 q = st4c[m];
    int s = cmp_ge_mask(u, q.x) + cmp_ge_mask(u, q.y)
          + cmp_ge_mask(u, q.z) + cmp_ge_mask(u, q.w);
    int j = m * 4 - s;
    return ab[j];
}

__global__ __launch_bounds__(THREADS)
void pixelwise_kernel(const float4* __restrict__ x,
                      const float* __restrict__ M,
                      const float* __restrict__ p_a,
                      const float* __restrict__ p_t,
                      const float* __restrict__ bias_c,
                      const float* __restrict__ bias,
                      float4* __restrict__ out) {
    __shared__ __align__(16) float sh_sxb[C * K];  // sorted breakpoints
    __shared__ float  sh_ss[C * K];                // slopes, sorted order
    __shared__ float  sh_xb[C * K];                // scratch
    __shared__ float  sh_s[C * K];                 // scratch
    __shared__ float  sh_cst[C * K];               // scale==0 constants
    __shared__ float2 sh_AB[C * 17];               // (A_j, B_j)
    __shared__ float  sh_scale[C];
    __shared__ float  sh_const;

    const int tid = threadIdx.x;
    const int i = blockIdx.x * (THREADS * PXT) + tid;

    // ---- hoist all 6 LDG.128 above the prologue ----
    const float4 v0a = x[i];
    const float4 v0b = x[i + THREADS];
    const float4 v1a = x[N4 + i];
    const float4 v1b = x[N4 + i + THREADS];
    const float4 v2a = x[2 * N4 + i];
    const float4 v2b = x[2 * N4 + i + THREADS];

    // ---- stage 1: transform (48 lanes) ----
    if (tid < C * K) {
        int c = tid / K;
        float scale = M[c * 3 + 0] + M[c * 3 + 1] + M[c * 3 + 2];
        float a = p_a[tid], t = p_t[tid], bc = bias_c[c];
        float xb, s, cst;
        if (scale != 0.0f) {
            xb  = (t - bc) / scale;
            s   = a * scale;
            cst = 0.0f;
        } else {
            xb = 0.0f; s = 0.0f;
            cst = a * fmaxf(bc - t, 0.0f);
        }
        sh_xb[tid]  = xb;
        sh_s[tid]   = s;
        sh_cst[tid] = cst;
        if (tid < C) sh_scale[tid] = scale;
    }
    __syncthreads();

    // ---- stage 2: rank sort per channel + CONST ----
    if (tid < C * K) {
        int c = tid / K, k = tid % K;
        float my = sh_xb[tid];
        int rank = 0;
        #pragma unroll
        for (int j = 0; j < K; j++) {
            float o = sh_xb[c * K + j];
            rank += (o < my || (o == my && j < k)) ? 1 : 0;
        }
        sh_sxb[c * K + rank] = my;
        sh_ss[c * K + rank]  = sh_s[tid];
    } else if (tid == C * K) {
        float v = bias[0];
        #pragma unroll
        for (int r = 0; r < C * K; r++) v += sh_cst[r];
        sh_const = v;
    }
    __syncthreads();

    // ---- stage 3: segment tables (51 lanes) ----
    if (tid < C * 17) {
        int c = tid / 17, j = tid % 17;
        bool pos = (sh_scale[c] >= 0.0f);
        float A = 0.0f, B = 0.0f;
        #pragma unroll
        for (int r = 0; r < K; r++) {
            float sv = sh_ss[c * K + r];
            float xv = sh_sxb[c * K + r];
            bool take = pos ? (r < j) : (r >= j);
            if (take) { A += sv; B -= sv * xv; }
        }
        if (c == 0) B += sh_const;
        sh_AB[tid] = make_float2(A, B);
    }
    __syncthreads();

    // ---- pivots into registers (broadcast LDS, once) ----
    const float4* st4 = (const float4*)sh_sxb;
    float pv[C][3];
    #pragma unroll
    for (int c = 0; c < C; c++) {
        pv[c][0] = sh_sxb[c * K + 3];
        pv[c][1] = sh_sxb[c * K + 7];
        pv[c][2] = sh_sxb[c * K + 11];
    }

    // ---- group A: pixels 0..3 ----
    {
        float ga[4][C] = {{v0a.x, v1a.x, v2a.x},
                          {v0a.y, v1a.y, v2a.y},
                          {v0a.z, v1a.z, v2a.z},
                          {v0a.w, v1a.w, v2a.w}};
        float accA[4] = {0.f,0.f,0.f,0.f};
        float accB[4] = {0.f,0.f,0.f,0.f};
        #pragma unroll
        for (int c = 0; c < C; c++) {
            const float4* st4c = &st4[c * 4];
            const float2* ab = &sh_AB[c * 17];
            #pragma unroll
            for (int p = 0; p < 4; p++) {
                float u = ga[p][c];
                float2 AB = pwl_coeff(u, pv[c][0], pv[c][1], pv[c][2], st4c, ab);
                accA[p] = fmaf(u, AB.x, accA[p]);
                accB[p] += AB.y;
            }
        }
        out[i] = make_float4(accA[0] + accB[0], accA[1] + accB[1],
                             accA[2] + accB[2], accA[3] + accB[3]);
    }

    // ---- group B: pixels 4..7 ----
    {
        float gb[4][C] = {{v0b.x, v1b.x, v2b.x},
                          {v0b.y, v1b.y, v2b.y},
                          {v0b.z, v1b.z, v2b.z},
                          {v0b.w, v1b.w, v2b.w}};
        float accA[4] = {0.f,0.f,0.f,0.f};
        float accB[4] = {0.f,0.f,0.f,0.f};
        #pragma unroll
        for (int c = 0; c < C; c++) {
            const float4* st4c = &st4[c * 4];
            const float2* ab = &sh_AB[c * 17];
            #pragma unroll
            for (int p = 0; p < 4; p++) {
                float u = gb[p][c];
                float2 AB = pwl_coeff(u, pv[c][0], pv[c][1], pv[c][2], st4c, ab);
                accA[p] = fmaf(u, AB.x, accA[p]);
                accB[p] += AB.y;
            }
        }
        out[i + THREADS] = make_float4(accA[0] + accB[0], accA[1] + accB[1],
                                       accA[2] + accB[2], accA[3] + accB[3]);
    }
}

extern "C" void kernel_launch(void* const* d_in, const int* in_sizes, int n_in,
                              void* d_out, int out_size) {
    const float4* x      = (const float4*)d_in[0];
    const float*  M      = (const float*)d_in[1];
    const float*  p_a    = (const float*)d_in[2];
    const float*  p_t    = (const float*)d_in[3];
    const float*  bias_c = (const float*)d_in[4];
    const float*  bias   = (const float*)d_in[5];
    float4* out = (float4*)d_out;

    pixelwise_kernel<<<BLOCKS, THREADS>>>(x, M, p_a, p_t, bias_c, bias, out);
}

// round 14
// speedup vs baseline: 1.5058x; 1.5058x over previous
#include <cuda_runtime.h>

// PixelWiseNet: out[h,w] = bias + sum_{c,k} p_a[c,k]*relu(x[c,h,w]*rowsum(M[c]) + bias_c[c] - p_t[c,k])
// C=3, H=W=1024, K=16.  Output [1024,1024] f32.
//
// PWL-in-x per channel: g_c(x) = A[j]*x + B[j], j = #{r: xb_r <= x} (xb sorted).
// Sign of scale folded into table build; bias + scale==0 constants in channel-0 B.
// Hot loop per value: 3 reg-pivot compares -> LDS.128 quartile -> 4 compares ->
// LDS.64 (A,B) -> FFMA + FADD.
//
// R13: R8 kernel with PXT=1 — 4 px/thread, grid 1024 (8192 warps, ~55/SM) to
// fix the grid-limited occupancy (R8: 3.46 blocks/SM -> 37% occ, issue 48%).
// Loads stay hoisted above the table-build prologue. Plain C compares (R11's
// PTX mask trick lowered to FSETP+SEL anyway and regressed).

#define C 3
#define K 16
#define HW (1024 * 1024)
#define N4 (HW / 4)
#define THREADS 256
#define BLOCKS (N4 / THREADS)    // 1024

__global__ __launch_bounds__(THREADS)
void pixelwise_kernel(const float4* __restrict__ x,
                      const float* __restrict__ M,
                      const float* __restrict__ p_a,
                      const float* __restrict__ p_t,
                      const float* __restrict__ bias_c,
                      const float* __restrict__ bias,
                      float4* __restrict__ out) {
    __shared__ __align__(16) float sh_sxb[C * K];  // sorted breakpoints
    __shared__ float  sh_ss[C * K];                // slopes, sorted order
    __shared__ float  sh_xb[C * K];                // scratch: unsorted breakpoints
    __shared__ float  sh_s[C * K];                 // scratch: unsorted slopes
    __shared__ float  sh_cst[C * K];               // scale==0 constants
    __shared__ float2 sh_AB[C * 17];               // (A_j, B_j)
    __shared__ float  sh_scale[C];
    __shared__ float  sh_const;

    const int tid = threadIdx.x;
    const int i = blockIdx.x * THREADS + tid;

    // ---- issue the 3 LDG.128 FIRST: in flight during the prologue ----
    const float4 v0 = x[i];
    const float4 v1 = x[N4 + i];
    const float4 v2 = x[2 * N4 + i];

    // ---- stage 1: transform (48 lanes) ----
    if (tid < C * K) {
        int c = tid / K;
        float scale = M[c * 3 + 0] + M[c * 3 + 1] + M[c * 3 + 2];
        float a = p_a[tid], t = p_t[tid], bc = bias_c[c];
        float xb, s, cst;
        if (scale != 0.0f) {
            xb  = (t - bc) / scale;
            s   = a * scale;
            cst = 0.0f;
        } else {
            xb = 0.0f; s = 0.0f;
            cst = a * fmaxf(bc - t, 0.0f);
        }
        sh_xb[tid]  = xb;
        sh_s[tid]   = s;
        sh_cst[tid] = cst;
        if (tid < C) sh_scale[tid] = scale;
    }
    __syncthreads();

    // ---- stage 2: rank sort per channel (48 lanes) + CONST (lane 48) ----
    if (tid < C * K) {
        int c = tid / K, k = tid % K;
        float my = sh_xb[tid];
        int rank = 0;
        #pragma unroll
        for (int j = 0; j < K; j++) {
            float o = sh_xb[c * K + j];
            rank += (o < my || (o == my && j < k)) ? 1 : 0;
        }
        sh_sxb[c * K + rank] = my;
        sh_ss[c * K + rank]  = sh_s[tid];
    } else if (tid == C * K) {
        float v = bias[0];
        #pragma unroll
        for (int r = 0; r < C * K; r++) v += sh_cst[r];
        sh_const = v;
    }
    __syncthreads();

    // ---- stage 3: segment tables (51 lanes) ----
    if (tid < C * 17) {
        int c = tid / 17, j = tid % 17;
        bool pos = (sh_scale[c] >= 0.0f);
        float A = 0.0f, B = 0.0f;
        #pragma unroll
        for (int r = 0; r < K; r++) {
            float sv = sh_ss[c * K + r];
            float xv = sh_sxb[c * K + r];
            bool take = pos ? (r < j) : (r >= j);
            if (take) { A += sv; B -= sv * xv; }
        }
        if (c == 0) B += sh_const;
        sh_AB[tid] = make_float2(A, B);
    }
    __syncthreads();

    // ---- main: 4 pixels per thread ----
    const float4* st4 = (const float4*)sh_sxb;

    float xs[C][4];
    xs[0][0]=v0.x; xs[0][1]=v0.y; xs[0][2]=v0.z; xs[0][3]=v0.w;
    xs[1][0]=v1.x; xs[1][1]=v1.y; xs[1][2]=v1.z; xs[1][3]=v1.w;
    xs[2][0]=v2.x; xs[2][1]=v2.y; xs[2][2]=v2.z; xs[2][3]=v2.w;

    float accA[4] = {0.f,0.f,0.f,0.f};
    float accB[4] = {0.f,0.f,0.f,0.f};

    #pragma unroll
    for (int c = 0; c < C; c++) {
        // block-uniform pivots -> registers (broadcast LDS)
        const float p0 = sh_sxb[c * K + 3];
        const float p1 = sh_sxb[c * K + 7];
        const float p2 = sh_sxb[c * K + 11];
        const float2* ab = &sh_AB[c * 17];

        #pragma unroll
        for (int p = 0; p < 4; p++) {
            float u = xs[c][p];
            int m = (u >= p0) + (u >= p1) + (u >= p2);
            float4 q = st4[c * 4 + m];
            int j = m * 4 + (u >= q.x) + (u >= q.y) + (u >= q.z) + (u >= q.w);
            float2 AB = ab[j];
            accA[p] = fmaf(u, AB.x, accA[p]);
            accB[p] += AB.y;
        }
    }

    out[i] = make_float4(accA[0] + accB[0], accA[1] + accB[1],
                         accA[2] + accB[2], accA[3] + accB[3]);
}

extern "C" void kernel_launch(void* const* d_in, const int* in_sizes, int n_in,
                              void* d_out, int out_size) {
    const float4* x      = (const float4*)d_in[0];
    const float*  M      = (const float*)d_in[1];
    const float*  p_a    = (const float*)d_in[2];
    const float*  p_t    = (const float*)d_in[3];
    const float*  bias_c = (const float*)d_in[4];
    const float*  bias   = (const float*)d_in[5];
    float4* out = (float4*)d_out;

    pixelwise_kernel<<<BLOCKS, THREADS>>>(x, M, p_a, p_t, bias_c, bias, out);
}